// round 3
// baseline (speedup 1.0000x reference)
#include <cuda_runtime.h>
#include <cuda_bf16.h>
#include <cstdint>

#define NIN   128
#define HID   256
#define NB    16
#define NOUT  2048
#define TM    128

// SMEM layout (bytes):
//   sHi  @ 0      : 128*132*4 = 67584   (inter hi pairs stride 68, then h hi pairs stride 132)
//   sLo  @ 67584  : 67584
//   sBas @ 135168 : 128*17*4 = 8704
//   sOut @ 143872 : 128*132*4 = 67584
#define SMEM_BYTES 211456

// -------- device scratch (no cudaMalloc allowed) --------
__device__ unsigned g_W1hi[64 * HID];     // W1 [128,256] -> k-pair packed bf16 hi
__device__ unsigned g_W1lo[64 * HID];
__device__ unsigned g_W2hi[128 * NOUT];   // W2 [256,2048] -> k-pair packed bf16 hi
__device__ unsigned g_W2lo[128 * NOUT];
__device__ int g_idx64;

// -------- helpers --------
__device__ __forceinline__ unsigned pk(float x0, float x1, unsigned &lo) {
    __nv_bfloat16 h0 = __float2bfloat16(x0), h1 = __float2bfloat16(x1);
    float r0 = x0 - __bfloat162float(h0);
    float r1 = x1 - __bfloat162float(h1);
    __nv_bfloat16 l0 = __float2bfloat16(r0), l1 = __float2bfloat16(r1);
    lo = ((unsigned)__bfloat16_as_ushort(l1) << 16) | (unsigned)__bfloat16_as_ushort(l0);
    return ((unsigned)__bfloat16_as_ushort(h1) << 16) | (unsigned)__bfloat16_as_ushort(h0);
}

__device__ __forceinline__ void mma16816(float (&d)[4], const unsigned (&a)[4], const unsigned (&b)[2]) {
    asm volatile(
        "mma.sync.aligned.m16n8k16.row.col.f32.bf16.bf16.f32 "
        "{%0,%1,%2,%3},{%4,%5,%6,%7},{%8,%9},{%0,%1,%2,%3};\n"
        : "+f"(d[0]), "+f"(d[1]), "+f"(d[2]), "+f"(d[3])
        : "r"(a[0]), "r"(a[1]), "r"(a[2]), "r"(a[3]), "r"(b[0]), "r"(b[1]));
}

// -------- prep kernels --------
__global__ void detect_idx_kernel(const unsigned* __restrict__ idx_raw) {
    if (threadIdx.x == 0) {
        unsigned nz = 0;
        #pragma unroll 1
        for (int k = 0; k < 64; k++) nz |= idx_raw[2 * k + 1];
        g_idx64 = (nz == 0) ? 1 : 0;  // int64 values < 2^31 -> high words all zero
    }
}

__global__ void prep_w1_kernel(const float* __restrict__ W1) {
    int i = blockIdx.x * blockDim.x + threadIdx.x;
    if (i >= 64 * HID) return;
    int k2 = i / HID, n = i % HID;
    float x0 = W1[(2 * k2) * HID + n];
    float x1 = W1[(2 * k2 + 1) * HID + n];
    unsigned lo; unsigned hi = pk(x0, x1, lo);
    g_W1hi[i] = hi; g_W1lo[i] = lo;
}

__global__ void prep_w2_kernel(const float* __restrict__ W2) {
    int i = blockIdx.x * blockDim.x + threadIdx.x;
    if (i >= 128 * NOUT) return;
    int k2 = i / NOUT, n = i % NOUT;
    float x0 = W2[(2 * k2) * NOUT + n];
    float x1 = W2[(2 * k2 + 1) * NOUT + n];
    unsigned lo; unsigned hi = pk(x0, x1, lo);
    g_W2hi[i] = hi; g_W2lo[i] = lo;
}

// -------- main fused kernel: one CTA per 128-edge tile --------
__global__ void __launch_bounds__(256, 1) pilayer_kernel(
    const float* __restrict__ prop, const void* __restrict__ idxi_raw,
    const void* __restrict__ idxj_raw, const float* __restrict__ basis,
    float* __restrict__ out, int P)
{
    extern __shared__ char smem[];
    unsigned* sHi = (unsigned*)smem;
    unsigned* sLo = (unsigned*)(smem + 67584);
    float*    sBas = (float*)(smem + 135168);
    float*    sOut = (float*)(smem + 143872);

    const int tid = threadIdx.x;
    const int w = tid >> 5, lane = tid & 31, q = lane & 3, r = lane >> 2;
    const int m0 = blockIdx.x * TM;
    const int mvalid = min(TM, P - m0);
    const bool is64 = (g_idx64 != 0);

    // ---- gather: inter = prop[idx_i] + prop[idx_j]; split bf16 hi/lo, pack k-pairs ----
    {
        int m = tid >> 1, half = tid & 1;
        unsigned* dh = sHi + m * 68 + half * 32;
        unsigned* dl = sLo + m * 68 + half * 32;
        if (m < mvalid) {
            long e = (long)(m0 + m);
            long ii, jj;
            if (is64) { ii = ((const long long*)idxi_raw)[e]; jj = ((const long long*)idxj_raw)[e]; }
            else      { ii = ((const int*)idxi_raw)[e];       jj = ((const int*)idxj_raw)[e]; }
            const float4* pi = (const float4*)(prop + ii * NIN) + half * 16;
            const float4* pj = (const float4*)(prop + jj * NIN) + half * 16;
            #pragma unroll
            for (int v = 0; v < 16; v++) {
                float4 a = pi[v]; float4 b = pj[v];
                unsigned lo0, lo1;
                unsigned hi0 = pk(a.x + b.x, a.y + b.y, lo0);
                unsigned hi1 = pk(a.z + b.z, a.w + b.w, lo1);
                dh[2 * v] = hi0; dh[2 * v + 1] = hi1;
                dl[2 * v] = lo0; dl[2 * v + 1] = lo1;
            }
        } else {
            #pragma unroll
            for (int v = 0; v < 32; v++) { dh[v] = 0u; dl[v] = 0u; }
        }
        // basis rows (zero-padded past mvalid)
        int off = half * 8;
        float4 b0, b1;
        if (m < mvalid) {
            const float4* bp = (const float4*)(basis + (long)(m0 + m) * NB + off);
            b0 = bp[0]; b1 = bp[1];
        } else { b0 = make_float4(0.f, 0.f, 0.f, 0.f); b1 = b0; }
        float* bd = sBas + m * 17 + off;
        bd[0] = b0.x; bd[1] = b0.y; bd[2] = b0.z; bd[3] = b0.w;
        bd[4] = b1.x; bd[5] = b1.y; bd[6] = b1.z; bd[7] = b1.w;
    }
    __syncthreads();

    float acc[8][4][4];

    // ---- GEMM1: pre = inter @ W1  (M=128, N=256, K=128), bf16x3 ----
    #pragma unroll
    for (int mt = 0; mt < 8; mt++)
        #pragma unroll
        for (int nt = 0; nt < 4; nt++)
            #pragma unroll
            for (int e = 0; e < 4; e++) acc[mt][nt][e] = 0.f;

    const int ncol0 = w * 32 + r;
    #pragma unroll 1
    for (int ks = 0; ks < 8; ks++) {
        const int kp = ks * 8;
        unsigned bhi[4][2], blo[4][2];
        #pragma unroll
        for (int nt = 0; nt < 4; nt++) {
            int c0 = (kp + q) * HID + ncol0 + nt * 8;
            int c1 = (kp + 4 + q) * HID + ncol0 + nt * 8;
            bhi[nt][0] = g_W1hi[c0]; bhi[nt][1] = g_W1hi[c1];
            blo[nt][0] = g_W1lo[c0]; blo[nt][1] = g_W1lo[c1];
        }
        #pragma unroll
        for (int mt = 0; mt < 8; mt++) {
            unsigned ahi[4], alo[4];
            const unsigned* p0 = sHi + (mt * 16 + r) * 68 + kp + q;
            const unsigned* p1 = sHi + (mt * 16 + r + 8) * 68 + kp + q;
            ahi[0] = p0[0]; ahi[1] = p1[0]; ahi[2] = p0[4]; ahi[3] = p1[4];
            const unsigned* q0 = sLo + (mt * 16 + r) * 68 + kp + q;
            const unsigned* q1 = sLo + (mt * 16 + r + 8) * 68 + kp + q;
            alo[0] = q0[0]; alo[1] = q1[0]; alo[2] = q0[4]; alo[3] = q1[4];
            #pragma unroll
            for (int nt = 0; nt < 4; nt++) {
                mma16816(acc[mt][nt], ahi, bhi[nt]);
                mma16816(acc[mt][nt], ahi, blo[nt]);
                mma16816(acc[mt][nt], alo, bhi[nt]);
            }
        }
    }
    __syncthreads();  // all inter reads complete before h overwrites the region

    // ---- tanh + split + store h (k-pair packed, stride 132) ----
    #pragma unroll
    for (int mt = 0; mt < 8; mt++) {
        int row0 = mt * 16 + r;
        #pragma unroll
        for (int nt = 0; nt < 4; nt++) {
            int cp = w * 16 + nt * 4 + q;  // k-pair index in [0,128)
            unsigned lo;
            unsigned hi = pk(tanhf(acc[mt][nt][0]), tanhf(acc[mt][nt][1]), lo);
            sHi[row0 * 132 + cp] = hi; sLo[row0 * 132 + cp] = lo;
            hi = pk(tanhf(acc[mt][nt][2]), tanhf(acc[mt][nt][3]), lo);
            sHi[(row0 + 8) * 132 + cp] = hi; sLo[(row0 + 8) * 132 + cp] = lo;
        }
    }
    __syncthreads();

    // ---- GEMM2 (M=128, N=2048 in 8 passes of 256, K=256) + fused basis epilogue ----
    #pragma unroll 1
    for (int pass = 0; pass < 8; pass++) {
        #pragma unroll
        for (int mt = 0; mt < 8; mt++)
            #pragma unroll
            for (int nt = 0; nt < 4; nt++)
                #pragma unroll
                for (int e = 0; e < 4; e++) acc[mt][nt][e] = 0.f;

        const int jbase = pass * 256 + w * 32 + r;
        #pragma unroll 1
        for (int ks = 0; ks < 16; ks++) {
            const int kp = ks * 8;
            unsigned bhi[4][2], blo[4][2];
            #pragma unroll
            for (int nt = 0; nt < 4; nt++) {
                int c0 = (kp + q) * NOUT + jbase + nt * 8;
                int c1 = (kp + 4 + q) * NOUT + jbase + nt * 8;
                bhi[nt][0] = g_W2hi[c0]; bhi[nt][1] = g_W2hi[c1];
                blo[nt][0] = g_W2lo[c0]; blo[nt][1] = g_W2lo[c1];
            }
            #pragma unroll
            for (int mt = 0; mt < 8; mt++) {
                unsigned ahi[4], alo[4];
                const unsigned* p0 = sHi + (mt * 16 + r) * 132 + kp + q;
                const unsigned* p1 = sHi + (mt * 16 + r + 8) * 132 + kp + q;
                ahi[0] = p0[0]; ahi[1] = p1[0]; ahi[2] = p0[4]; ahi[3] = p1[4];
                const unsigned* q0 = sLo + (mt * 16 + r) * 132 + kp + q;
                const unsigned* q1 = sLo + (mt * 16 + r + 8) * 132 + kp + q;
                alo[0] = q0[0]; alo[1] = q1[0]; alo[2] = q0[4]; alo[3] = q1[4];
                #pragma unroll
                for (int nt = 0; nt < 4; nt++) {
                    mma16816(acc[mt][nt], ahi, bhi[nt]);
                    mma16816(acc[mt][nt], ahi, blo[nt]);
                    mma16816(acc[mt][nt], alo, bhi[nt]);
                }
            }
        }
        // epilogue: out[m][c] = sum_b H[m][16c+b]*basis[m][b]; each (pass,warp,tp) owns c exclusively
        #pragma unroll
        for (int mt = 0; mt < 8; mt++) {
            int row0 = mt * 16 + r, row1 = row0 + 8;
            float b00 = sBas[row0 * 17 + 2 * q],     b01 = sBas[row0 * 17 + 2 * q + 1];
            float b08 = sBas[row0 * 17 + 8 + 2 * q], b09 = sBas[row0 * 17 + 9 + 2 * q];
            float b10 = sBas[row1 * 17 + 2 * q],     b11 = sBas[row1 * 17 + 2 * q + 1];
            float b18 = sBas[row1 * 17 + 8 + 2 * q], b19 = sBas[row1 * 17 + 9 + 2 * q];
            #pragma unroll
            for (int tp = 0; tp < 2; tp++) {
                float s0 = acc[mt][2 * tp][0] * b00 + acc[mt][2 * tp][1] * b01
                         + acc[mt][2 * tp + 1][0] * b08 + acc[mt][2 * tp + 1][1] * b09;
                float s1 = acc[mt][2 * tp][2] * b10 + acc[mt][2 * tp][3] * b11
                         + acc[mt][2 * tp + 1][2] * b18 + acc[mt][2 * tp + 1][3] * b19;
                s0 += __shfl_xor_sync(0xffffffffu, s0, 1);
                s0 += __shfl_xor_sync(0xffffffffu, s0, 2);
                s1 += __shfl_xor_sync(0xffffffffu, s1, 1);
                s1 += __shfl_xor_sync(0xffffffffu, s1, 2);
                if (q == 0) {
                    int c = pass * 16 + w * 2 + tp;
                    sOut[row0 * 132 + c] = s0;
                    sOut[row1 * 132 + c] = s1;
                }
            }
        }
    }
    __syncthreads();

    // ---- coalesced output store ----
    #pragma unroll 1
    for (int i = tid; i < TM * 32; i += 256) {
        int m = i >> 5, c4 = i & 31;
        if (m < mvalid) {
            const float4 v = *(const float4*)(sOut + m * 132 + c4 * 4);
            *(float4*)(out + ((long)(m0 + m)) * NIN + c4 * 4) = v;
        }
    }
}

extern "C" void kernel_launch(void* const* d_in, const int* in_sizes, int n_in,
                              void* d_out, int out_size) {
    const float* prop  = (const float*)d_in[0];
    const void*  idxi  = d_in[1];
    const void*  idxj  = d_in[2];
    const float* basis = (const float*)d_in[3];
    const float* W1    = (const float*)d_in[4];
    const float* W2    = (const float*)d_in[5];
    float* out = (float*)d_out;
    const int P = out_size / NIN;
    (void)in_sizes; (void)n_in;

    cudaFuncSetAttribute(pilayer_kernel, cudaFuncAttributeMaxDynamicSharedMemorySize, SMEM_BYTES);

    detect_idx_kernel<<<1, 32>>>((const unsigned*)idxi);
    prep_w1_kernel<<<(64 * HID + 255) / 256, 256>>>(W1);
    prep_w2_kernel<<<(128 * NOUT + 255) / 256, 256>>>(W2);

    const int blocks = (P + TM - 1) / TM;
    pilayer_kernel<<<blocks, 256, SMEM_BYTES>>>(prop, idxi, idxj, basis, out, P);
}